// round 17
// baseline (speedup 1.0000x reference)
#include <cuda_runtime.h>

#define HIDDEN 8
#define RES 64
#define NBATCH 2048
#define TILE_H 16
#define SROWS 20           // TILE_H + 4 halo rows
#define SROW 72            // padded smem row stride (floats): cols 0..67 used
#define SP_FLOATS (HIDDEN * SROWS * SROW)
// conv weights: 3 symmetric rows x 5 taps, rows padded to 8 slots -> 32/channel
#define SMEM_FLOATS (SP_FLOATS + 256 + 64 + 64 + 8 + 8 + 8)
#define SMEM_BYTES (SMEM_FLOATS * 4)

// D4-symmetrized, per-kernel-zero-mean 5x5 depthwise weights
__device__ float g_w[HIDDEN * 25];

__global__ void prep_weights_kernel(const float* __restrict__ filter1) {
    __shared__ float sw[HIDDEN * 25];
    int t = threadIdx.x;
    float wv = 0.f;
    int h = 0;
    if (t < 200) {
        h = t / 25;
        int idx = t % 25;
        int i = idx / 5, j = idx % 5;
        const float* f = filter1 + h * 25;
        float s = f[i*5 + j] + f[(4-i)*5 + j] + f[i*5 + (4-j)] + f[(4-i)*5 + (4-j)]
                + f[j*5 + i] + f[(4-j)*5 + i] + f[j*5 + (4-i)] + f[(4-j)*5 + (4-i)];
        wv = 0.125f * s;
        sw[t] = wv;
    }
    __syncthreads();
    if (t < 200) {
        float m = 0.f;
        #pragma unroll
        for (int k = 0; k < 25; k++) m += sw[h * 25 + k];
        g_w[t] = wv - m * (1.0f / 25.0f);
    }
}

// 2-op leaky_relu: FMUL + FFMA (|x| folds into the FFMA operand modifier).
__device__ __forceinline__ float lrelu(float x) {
    return fmaf(0.495f, fabsf(x), 0.505f * x);
}
__device__ __forceinline__ float tanh_fast(float x) {
    float y;
    asm("tanh.approx.f32 %0, %1;" : "=f"(y) : "f"(x));
    return y;
}

__global__ __launch_bounds__(256, 4)
void ca_fused_kernel(const float* __restrict__ psi,
                     const float* __restrict__ bias1,
                     const float* __restrict__ w2,
                     const float* __restrict__ b2,
                     const float* __restrict__ w3,
                     const float* __restrict__ b3,
                     float* __restrict__ out)
{
    extern __shared__ __align__(16) float sm[];
    float* sp  = sm;                 // planar psi tile, pixel x at col x+2
    float* swt = sm + SP_FLOATS;     // conv weights: [ch*32 + r*8 + dx], r<3, dx<5
    float* sw2 = swt + 256;          // 64 (transposed: sw2[i*8+o] = w2[o][i])
    float* sw3 = sw2 + 64;           // 64 (row-major: sw3[o*8+i])
    float* sb1 = sw3 + 64;           // 8
    float* sb2 = sb1 + 8;            // 8
    float* sb3 = sb2 + 8;            // 8

    const int tid = threadIdx.x;
    const int b   = blockIdx.y;
    const int y0  = blockIdx.x * TILE_H;

    // ---- stage small params into smem ----
    // Conv weights, 8-slot padded rows so each row is one aligned float4 + scalar.
    {
        int ch = tid >> 5, k = tid & 31;      // all 256 threads cover 8ch x 32
        int r = k >> 3, dx = k & 7;
        swt[tid] = (r < 3 && dx < 5) ? g_w[ch * 25 + r * 5 + dx] : 0.f;
    }
    if (tid < 64) {
        int o = tid >> 3, i = tid & 7;
        sw2[i * 8 + o] = w2[tid];
    } else if (tid >= 128 && tid < 192)  sw3[tid - 128] = w3[tid - 128];
    else if (tid >= 192 && tid < 200)    sb1[tid - 192] = bias1[tid - 192];
    else if (tid >= 200 && tid < 208)    sb2[tid - 200] = b2[tid - 200];
    else if (tid >= 208 && tid < 216)    sb3[tid - 208] = b3[tid - 208];

    // ---- zero the x-halo columns (cols 0,1,66,67) ----
    for (int k = tid; k < HIDDEN * SROWS * 4; k += 256) {
        int c  = k & 3;
        int rr = k >> 2;                    // ch*SROWS + r
        int col = (c < 2) ? c : (64 + c);   // 0,1,66,67
        sp[rr * SROW + col] = 0.f;
    }

    // ---- interior fill: float4 global loads, zero rows outside the image ----
    const float* pb = psi + (size_t)b * (HIDDEN * RES * RES);
    for (int k = tid; k < HIDDEN * SROWS * 16; k += 256) {
        int q  = k & 15;                     // float4 index within row
        int rr = k >> 4;                     // ch*SROWS + r
        int r  = rr % SROWS;
        int ch = rr / SROWS;
        int gy = y0 + r - 2;
        float4 v = make_float4(0.f, 0.f, 0.f, 0.f);
        if ((unsigned)gy < RES)
            v = *(const float4*)(pb + (ch * RES + gy) * RES + q * 4);
        float2* d = (float2*)(sp + rr * SROW + q * 4 + 2);   // col = x+2 (8B aligned)
        d[0] = make_float2(v.x, v.y);
        d[1] = make_float2(v.z, v.w);
    }
    __syncthreads();

    // Each thread: 4 x-pixels (x0..x0+3) of ONE output row (ry), all 8 channels.
    const int tx = tid & 15;
    const int ry = tid >> 4;     // output row within tile (0..15)
    const int x0 = tx << 2;      // output x base (0..60)

    // GEMM1 accumulators; conv fused into the channel loop so z never stores.
    float z2[8][4];
    #pragma unroll
    for (int o = 0; o < 8; o++) {
        float bv = sb2[o];
        z2[o][0] = bv; z2[o][1] = bv; z2[o][2] = bv; z2[o][3] = bv;
    }

    #pragma unroll
    for (int ch = 0; ch < 8; ch++) {
        const float* base = sp + (ch * SROWS + ry) * SROW + x0;  // col x0 == pixel x0-2
        const float* wch  = swt + ch * 32;

        float bv = sb1[ch];
        float a0 = bv, a1 = bv, a2 = bv, a3 = bv;

        // Row-pair at a time (register-lean): vertical symmetry row4==row0,
        // row3==row1. Fold each pair immediately, then 5 taps x 4 px.
        #pragma unroll
        for (int r = 0; r < 3; r++) {
            float4 A = *(const float4*)(base + r * SROW);
            float4 B = *(const float4*)(base + r * SROW + 4);
            float t[8];
            if (r < 2) {
                float4 C = *(const float4*)(base + (4 - r) * SROW);
                float4 D = *(const float4*)(base + (4 - r) * SROW + 4);
                t[0] = A.x + C.x; t[1] = A.y + C.y; t[2] = A.z + C.z; t[3] = A.w + C.w;
                t[4] = B.x + D.x; t[5] = B.y + D.y; t[6] = B.z + D.z; t[7] = B.w + D.w;
            } else {
                t[0] = A.x; t[1] = A.y; t[2] = A.z; t[3] = A.w;
                t[4] = B.x; t[5] = B.y; t[6] = B.z; t[7] = B.w;
            }
            // Row weights: one aligned LDS.128 + one LDS.32 (vs 5 scalar LDS).
            float4 W  = *(const float4*)(wch + r * 8);
            float  w4 = wch[r * 8 + 4];
            a0 = fmaf(W.x, t[0], a0); a1 = fmaf(W.x, t[1], a1);
            a2 = fmaf(W.x, t[2], a2); a3 = fmaf(W.x, t[3], a3);
            a0 = fmaf(W.y, t[1], a0); a1 = fmaf(W.y, t[2], a1);
            a2 = fmaf(W.y, t[3], a2); a3 = fmaf(W.y, t[4], a3);
            a0 = fmaf(W.z, t[2], a0); a1 = fmaf(W.z, t[3], a1);
            a2 = fmaf(W.z, t[4], a2); a3 = fmaf(W.z, t[5], a3);
            a0 = fmaf(W.w, t[3], a0); a1 = fmaf(W.w, t[4], a1);
            a2 = fmaf(W.w, t[5], a2); a3 = fmaf(W.w, t[6], a3);
            a0 = fmaf(w4,  t[4], a0); a1 = fmaf(w4,  t[5], a1);
            a2 = fmaf(w4,  t[6], a2); a3 = fmaf(w4,  t[7], a3);
        }
        float v0 = lrelu(a0), v1 = lrelu(a1), v2 = lrelu(a2), v3 = lrelu(a3);

        // fused GEMM1 accumulation: two aligned LDS.128 fetch all 8 weights.
        float4 uA = *(const float4*)(sw2 + ch * 8);
        float4 uB = *(const float4*)(sw2 + ch * 8 + 4);
        float uw[8] = {uA.x, uA.y, uA.z, uA.w, uB.x, uB.y, uB.z, uB.w};
        #pragma unroll
        for (int o = 0; o < 8; o++) {
            float ww = uw[o];
            z2[o][0] = fmaf(ww, v0, z2[o][0]);
            z2[o][1] = fmaf(ww, v1, z2[o][1]);
            z2[o][2] = fmaf(ww, v2, z2[o][2]);
            z2[o][3] = fmaf(ww, v3, z2[o][3]);
        }
    }

    // leaky_relu on z2
    #pragma unroll
    for (int o = 0; o < 8; o++) {
        z2[o][0] = lrelu(z2[o][0]);
        z2[o][1] = lrelu(z2[o][1]);
        z2[o][2] = lrelu(z2[o][2]);
        z2[o][3] = lrelu(z2[o][3]);
    }

    // GEMM2 per output channel (4 live accumulators) + residual (global, L1-hot)
    // + tanh + store
    float* ob = out + (size_t)b * (HIDDEN * RES * RES);
    const int gy = y0 + ry;
    #pragma unroll
    for (int o = 0; o < 8; o++) {
        // all 8 row weights via two aligned LDS.128
        float4 wA = *(const float4*)(sw3 + o * 8);
        float4 wB = *(const float4*)(sw3 + o * 8 + 4);
        float uw[8] = {wA.x, wA.y, wA.z, wA.w, wB.x, wB.y, wB.z, wB.w};
        float h0 = sb3[o], h1 = h0, h2 = h0, h3 = h0;
        #pragma unroll
        for (int i = 0; i < 8; i++) {
            float ww = uw[i];
            h0 = fmaf(ww, z2[i][0], h0);
            h1 = fmaf(ww, z2[i][1], h1);
            h2 = fmaf(ww, z2[i][2], h2);
            h3 = fmaf(ww, z2[i][3], h3);
        }
        float4 pv = *(const float4*)(pb + (o * RES + gy) * RES + x0);
        float4 res;
        res.x = tanh_fast(pv.x + h0);
        res.y = tanh_fast(pv.y + h1);
        res.z = tanh_fast(pv.z + h2);
        res.w = tanh_fast(pv.w + h3);
        *(float4*)(ob + (o * RES + gy) * RES + x0) = res;
    }
}

extern "C" void kernel_launch(void* const* d_in, const int* in_sizes, int n_in,
                              void* d_out, int out_size) {
    const float* psi     = (const float*)d_in[0];
    const float* filter1 = (const float*)d_in[1];
    const float* bias1   = (const float*)d_in[2];
    const float* w2      = (const float*)d_in[3];
    const float* b2      = (const float*)d_in[4];
    const float* w3      = (const float*)d_in[5];
    const float* b3      = (const float*)d_in[6];
    float* out = (float*)d_out;

    cudaFuncSetAttribute(ca_fused_kernel,
                         cudaFuncAttributeMaxDynamicSharedMemorySize, SMEM_BYTES);

    prep_weights_kernel<<<1, 256>>>(filter1);

    dim3 grid(RES / TILE_H, NBATCH);
    ca_fused_kernel<<<grid, 256, SMEM_BYTES>>>(psi, bias1, w2, b2, w3, b3, out);
}